// round 3
// baseline (speedup 1.0000x reference)
#include <cuda_runtime.h>

#define BB 4
#define CC 84
#define CP 80          // channels participating in the max (points[:, :-4])
#define HH 512
#define WW 512
#define HW (HH * WW)   // 262144

#define TR 16          // interior tile rows
#define TC 32          // interior tile cols (warp-width -> coalesced)
#define PRr (TR + 2)   // padded rows
#define PCc (TC + 2)   // padded cols
#define NP (PRr * PCc) // 612 padded positions
#define NT (TR * TC)   // 512 threads per CTA

// ---------------------------------------------------------------------------
// One padded position: compute probs = max over 80 channels (0 outside image).
// Interior positions also cache all 80 channel values into shared memory.
// ---------------------------------------------------------------------------
__device__ __forceinline__ void do_pos(int p, int bx, int by, int b,
                                       const float* __restrict__ pts,
                                       float* __restrict__ s_ch,
                                       float* __restrict__ s_pr) {
    int pr = p / PCc;
    int pc = p - pr * PCc;
    int gh = by * TR + pr - 1;
    int gw = bx * TC + pc - 1;
    bool interior = (pr >= 1) & (pr <= TR) & (pc >= 1) & (pc <= TC);
    bool inb = (gh >= 0) & (gh < HH) & (gw >= 0) & (gw < WW);

    float m = 0.0f;                       // zero-padding outside the image
    if (inb) {
        const float* base = pts + ((size_t)b * CC) * HW + (size_t)gh * WW + gw;
        float mm = -3.402823466e38f;
        if (interior) {
            int iidx = (pr - 1) * TC + (pc - 1);
            #pragma unroll
            for (int c = 0; c < CP; ++c) {
                float v = base[(size_t)c * HW];
                s_ch[c * NT + iidx] = v;
                mm = fmaxf(mm, v);
            }
        } else {
            #pragma unroll 16
            for (int c = 0; c < CP; ++c)
                mm = fmaxf(mm, base[(size_t)c * HW]);
        }
        m = mm;
    }
    s_pr[p] = m;
}

// ---------------------------------------------------------------------------
// Fused: channel-max (+ SMEM cache) -> local 3x3 NMS mask -> apply & write.
// grid (WW/TC, HH/TR, BB), block NT=512, dynamic smem 166 KB.
// ---------------------------------------------------------------------------
__global__ void __launch_bounds__(NT, 1)
fused_nms_kernel(const float* __restrict__ pts, float* __restrict__ out) {
    extern __shared__ float smem[];
    float* s_ch = smem;            // [CP][NT] channel cache for interior pixels
    float* s_pr = smem + CP * NT;  // [NP] padded probs tile

    const int tid = threadIdx.x;
    const int bx = blockIdx.x, by = blockIdx.y, b = blockIdx.z;

    // Phase 1: 612 padded positions covered by 512 threads (first 100 do two).
    do_pos(tid, bx, by, b, pts, s_ch, s_pr);
    if (tid < NP - NT)
        do_pos(tid + NT, bx, by, b, pts, s_ch, s_pr);

    // Prefetch the 4 tail channels (80..83) for this thread's own pixel.
    const int r  = tid >> 5;       // 0..15
    const int cc = tid & 31;       // 0..31
    const int gh = by * TR + r;
    const int gw = bx * TC + cc;
    const size_t pixoff = ((size_t)b * CC) * HW + (size_t)gh * WW + gw;
    float t80 = pts[pixoff + (size_t)(CP + 0) * HW];
    float t81 = pts[pixoff + (size_t)(CP + 1) * HW];
    float t82 = pts[pixoff + (size_t)(CP + 2) * HW];
    float t83 = pts[pixoff + (size_t)(CP + 3) * HW];

    __syncthreads();

    // Phase 2: 3x3 NMS mask from the padded probs tile.
    // neighbors before center: strict > ; after center: >=
    const int pr = r + 1, pc = cc + 1;
    const float* P = s_pr;
    float cen = P[pr * PCc + pc];
    bool ok = (cen >  P[(pr - 1) * PCc + (pc - 1)]) &
              (cen >  P[(pr - 1) * PCc +  pc     ]) &
              (cen >  P[(pr - 1) * PCc + (pc + 1)]) &
              (cen >  P[ pr      * PCc + (pc - 1)]) &
              (cen >= P[ pr      * PCc + (pc + 1)]) &
              (cen >= P[(pr + 1) * PCc + (pc - 1)]) &
              (cen >= P[(pr + 1) * PCc +  pc     ]) &
              (cen >= P[(pr + 1) * PCc + (pc + 1)]);
    float f = ok ? 1.0f : 0.0f;

    // Phase 3: write all 84 channels (first 80 from SMEM cache, no re-read).
    #pragma unroll
    for (int c = 0; c < CP; ++c)
        out[pixoff + (size_t)c * HW] = f * s_ch[c * NT + tid];
    out[pixoff + (size_t)(CP + 0) * HW] = f * t80;
    out[pixoff + (size_t)(CP + 1) * HW] = f * t81;
    out[pixoff + (size_t)(CP + 2) * HW] = f * t82;
    out[pixoff + (size_t)(CP + 3) * HW] = f * t83;
}

// ---------------------------------------------------------------------------
extern "C" void kernel_launch(void* const* d_in, const int* in_sizes, int n_in,
                              void* d_out, int out_size) {
    const float* pts = (const float*)d_in[0];
    float*       out = (float*)d_out;

    size_t shbytes = (size_t)(CP * NT + NP) * sizeof(float);   // 166288 B
    cudaFuncSetAttribute(fused_nms_kernel,
                         cudaFuncAttributeMaxDynamicSharedMemorySize,
                         (int)shbytes);

    dim3 grid(WW / TC, HH / TR, BB);   // (16, 32, 4)
    fused_nms_kernel<<<grid, NT, shbytes>>>(pts, out);
}